// round 17
// baseline (speedup 1.0000x reference)
#include <cuda_runtime.h>
#include <cuda_bf16.h>
#include <math.h>
#include <stdint.h>

#define N_IMG  128
#define N_REG  36
#define N_CAP  128
#define N_WORD 32
#define DIM    1024
#define LAMBDA 20.0f
#define EPSV   1e-8f
#define SLOPE  0.1f

#define M_TOT 4608
#define N_TOT 4096
#define KCAT  3072
#define KB    (KCAT * 2)
#define NK2   48

__device__ __align__(256) __nv_bfloat16 d_Acat[(size_t)M_TOT * KCAT];
__device__ __align__(256) __nv_bfloat16 d_Bcat[(size_t)N_TOT * KCAT];
__device__ __align__(256) float d_Gi[N_IMG * N_REG * N_REG];
__device__ __align__(256) float d_Gc[N_CAP * N_WORD * N_WORD];

__device__ __forceinline__ float lrelu(float x) { return x > 0.f ? x : SLOPE * x; }

__device__ __forceinline__ uint32_t smem_u32(const void* p) {
    uint32_t a;
    asm("{ .reg .u64 t; cvta.to.shared.u64 t, %1; cvt.u32.u64 %0, t; }" : "=r"(a) : "l"(p));
    return a;
}
__device__ __forceinline__ void ffma2(uint64_t& d, uint64_t a, uint64_t b) {
    asm("fma.rn.f32x2 %0, %1, %2, %0;" : "+l"(d) : "l"(a), "l"(b));
}
__device__ __forceinline__ float f2sum(uint64_t v) {
    float lo, hi;
    asm("mov.b64 {%0, %1}, %2;" : "=f"(lo), "=f"(hi) : "l"(v));
    return lo + hi;
}
__device__ __forceinline__ uint64_t f2pack(float lo, float hi) {
    uint64_t v;
    asm("mov.b64 %0, {%1, %2};" : "=l"(v) : "f"(lo), "f"(hi));
    return v;
}

#define LDSM4(r0, r1, r2, r3, addr) \
    asm volatile("ldmatrix.sync.aligned.m8n8.x4.shared.b16 {%0,%1,%2,%3}, [%4];" \
        : "=r"(r0), "=r"(r1), "=r"(r2), "=r"(r3) : "r"(addr))

#define MMA16816(d, a, b) \
    asm volatile("mma.sync.aligned.m16n8k16.row.col.f32.bf16.bf16.f32 " \
        "{%0,%1,%2,%3}, {%4,%5,%6,%7}, {%8,%9}, {%0,%1,%2,%3};" \
        : "+f"((d)[0]), "+f"((d)[1]), "+f"((d)[2]), "+f"((d)[3]) \
        : "r"((a)[0]), "r"((a)[1]), "r"((a)[2]), "r"((a)[3]), "r"((b)[0]), "r"((b)[1]))

#define CP16(dst, src) \
    asm volatile("cp.async.cg.shared.global [%0], [%1], 16;" :: "r"(dst), "l"(src))

#define BAR_SYNC(id, cnt)   asm volatile("bar.sync " #id ", " #cnt ";" ::: "memory")
#define BAR_ARRIVE(id, cnt) asm volatile("bar.arrive " #id ", " #cnt ";" ::: "memory")

// ---------------------------------------------------------------------------
__global__ void prep_kernel(const float* __restrict__ X, int totalPairs, int sel) {
    int p = blockIdx.x * blockDim.x + threadIdx.x;
    if (p >= totalPairs) return;
    float2 v = *(const float2*)(X + 2 * (size_t)p);
    __nv_bfloat16 h0 = __float2bfloat16(v.x);
    __nv_bfloat16 h1 = __float2bfloat16(v.y);
    __nv_bfloat16 l0 = __float2bfloat16(v.x - __bfloat162float(h0));
    __nv_bfloat16 l1 = __float2bfloat16(v.y - __bfloat162float(h1));
    uint32_t hh = ((uint32_t)*(uint16_t*)&h1 << 16) | *(uint16_t*)&h0;
    uint32_t ll = ((uint32_t)*(uint16_t*)&l1 << 16) | *(uint16_t*)&l0;
    int row = p >> 9, kp = p & 511;
    uint32_t* out = (uint32_t*)(sel ? d_Bcat : d_Acat);
    size_t base = (size_t)row * (KCAT / 2) + kp;
    out[base] = hh;
    out[base + 512]  = sel ? ll : hh;
    out[base + 1024] = sel ? hh : ll;
}

// ---------------------------------------------------------------------------
__global__ __launch_bounds__(256)
void gram2_kernel(const float* __restrict__ imgs, const float* __restrict__ caps) {
    const int item = blockIdx.x;
    const bool isCap = item >= N_IMG;
    const float* X = isCap ? caps + (size_t)(item - N_IMG) * N_WORD * DIM
                           : imgs + (size_t)item * N_REG * DIM;
    const int R = isCap ? N_WORD : N_REG;

    __shared__ __align__(16) float xs[36][260];
    const int tid = threadIdx.x;
    const int tr = (tid % 12) * 3;
    const int tc = (tid / 12) * 2;
    const bool act = tid < 216;

    float acc00 = 0.f, acc01 = 0.f, acc10 = 0.f, acc11 = 0.f, acc20 = 0.f, acc21 = 0.f;

    for (int k0 = 0; k0 < DIM; k0 += 256) {
        __syncthreads();
        for (int idx = tid; idx < 36 * 64; idx += 256) {
            int r = idx >> 6, kq = idx & 63;
            float4 v = (r < R) ? ((const float4*)(X + (size_t)r * DIM + k0))[kq]
                               : make_float4(0.f, 0.f, 0.f, 0.f);
            *(float4*)&xs[r][kq * 4] = v;
        }
        __syncthreads();
        if (act) {
            const float4* A0 = (const float4*)xs[tr];
            const float4* A1 = (const float4*)xs[tr + 1];
            const float4* A2 = (const float4*)xs[tr + 2];
            const float4* B0 = (const float4*)xs[tc];
            const float4* B1 = (const float4*)xs[tc + 1];
#pragma unroll 8
            for (int kq = 0; kq < 64; kq++) {
                float4 a0 = A0[kq], a1 = A1[kq], a2 = A2[kq];
                float4 b0 = B0[kq], b1 = B1[kq];
                acc00 += a0.x * b0.x + a0.y * b0.y + a0.z * b0.z + a0.w * b0.w;
                acc01 += a0.x * b1.x + a0.y * b1.y + a0.z * b1.z + a0.w * b1.w;
                acc10 += a1.x * b0.x + a1.y * b0.y + a1.z * b0.z + a1.w * b0.w;
                acc11 += a1.x * b1.x + a1.y * b1.y + a1.z * b1.z + a1.w * b1.w;
                acc20 += a2.x * b0.x + a2.y * b0.y + a2.z * b0.z + a2.w * b0.w;
                acc21 += a2.x * b1.x + a2.y * b1.y + a2.z * b1.z + a2.w * b1.w;
            }
        }
    }
    if (act) {
        float* G = isCap ? d_Gc + (size_t)(item - N_IMG) * (N_WORD * N_WORD)
                         : d_Gi + (size_t)item * (N_REG * N_REG);
        float v[3][2] = {{acc00, acc01}, {acc10, acc11}, {acc20, acc21}};
#pragma unroll
        for (int i = 0; i < 3; i++)
#pragma unroll
            for (int j = 0; j < 2; j++) {
                int r = tr + i, c2 = tc + j;
                if (r < R && c2 < R) G[r * R + c2] = v[i][j];
            }
    }
}

// ---------------------------------------------------------------------------
// Warp-specialized fused kernel.
// 288 threads: warps 0-5 GEMM producer (tile 144x64, 2 tiles), warps 6-8
// attn consumer. Double-buffered S; named-barrier handoff.
// ---------------------------------------------------------------------------
#define FPITCH 144
#define STG    ((144 + 64) * FPITCH)           // 29952 per stage
#define OFF_S0 (3 * STG)                       // 89856
#define PS2    68
#define SBYTES (144 * PS2 * 4)                 // 39168
#define OFF_S1 (OFF_S0 + SBYTES)               // 129024
#define OFF_GI (OFF_S1 + SBYTES)               // 168192
#define OFF_GC (OFF_GI + 4 * 1296 * 4)         // 188928
#define OFF_MISC (OFF_GC + 4 * 1024 * 4)       // 205312
#define FSMEM  (OFF_MISC + 512)                // 205824

__global__ __launch_bounds__(288, 1)
void fused_kernel(float* __restrict__ out) {
    extern __shared__ char smem[];
    const uint32_t sb = smem_u32(smem);
    const int tid = threadIdx.x;
    const int mb = blockIdx.y * 144;

    if (tid < 192) {
        // ================= PRODUCER (6 warps) =================
        const int lane = tid & 31, wid = tid >> 5;
        const int wm = wid >> 1;       // 0..2, m offset *48
        const int wn = wid & 1;        // 0..1, n offset *32
        const uint32_t aoff = (uint32_t)((wm * 48 + (lane & 15)) * FPITCH + (lane >> 4) * 16);
        const uint32_t boff = (uint32_t)((wn * 32 + (lane & 7) + ((lane >> 4) & 1) * 8) * FPITCH
                                         + ((lane >> 3) & 1) * 16);
        const char* Ag = (const char*)d_Acat + (size_t)mb * KB;

        for (int tile = 0; tile < 2; tile++) {
            const int nb = blockIdx.x * 128 + tile * 64;
            const char* Bg = (const char*)d_Bcat + (size_t)nb * KB;

            float acc[3][4][4];
#pragma unroll
            for (int i = 0; i < 3; i++)
#pragma unroll
                for (int j = 0; j < 4; j++)
#pragma unroll
                    for (int q = 0; q < 4; q++) acc[i][j][q] = 0.f;

            auto load_stage = [&](int s, int kt) {
                const uint32_t sA = sb + s * STG;
                const uint32_t sB = sA + 144 * FPITCH;
                const char* Asrc = Ag + kt * 128;
                const char* Bsrc = Bg + kt * 128;
#pragma unroll
                for (int i = 0; i < 9; i++) {
                    int idx = tid + i * 192;
                    if (idx < 1664) {
                        if (idx < 1152) {
                            int row = idx >> 3, seg = idx & 7;
                            CP16(sA + row * FPITCH + seg * 16,
                                 Asrc + (size_t)row * KB + seg * 16);
                        } else {
                            int j = idx - 1152;
                            int row = j >> 3, seg = j & 7;
                            CP16(sB + row * FPITCH + seg * 16,
                                 Bsrc + (size_t)row * KB + seg * 16);
                        }
                    }
                }
            };

            load_stage(0, 0);
            asm volatile("cp.async.commit_group;" ::: "memory");
            load_stage(1, 1);
            asm volatile("cp.async.commit_group;" ::: "memory");

            for (int kt = 0; kt < NK2; kt++) {
                const int s = kt % 3;
                asm volatile("cp.async.wait_group 1;" ::: "memory");
                BAR_SYNC(3, 192);
                if (kt + 2 < NK2) load_stage((kt + 2) % 3, kt + 2);
                asm volatile("cp.async.commit_group;" ::: "memory");

                const uint32_t sA = sb + s * STG;
                const uint32_t sB = sA + 144 * FPITCH;
#pragma unroll
                for (int ks = 0; ks < 4; ks++) {
                    const uint32_t kbyte = (uint32_t)ks * 32;
                    uint32_t af[3][4];
#pragma unroll
                    for (int mi = 0; mi < 3; mi++)
                        LDSM4(af[mi][0], af[mi][1], af[mi][2], af[mi][3],
                              sA + aoff + mi * (16 * FPITCH) + kbyte);
                    uint32_t bfr[4][2];
#pragma unroll
                    for (int nt = 0; nt < 2; nt++) {
                        uint32_t r0, r1, r2, r3;
                        LDSM4(r0, r1, r2, r3, sB + boff + nt * (16 * FPITCH) + kbyte);
                        bfr[2 * nt][0] = r0;     bfr[2 * nt][1] = r1;
                        bfr[2 * nt + 1][0] = r2; bfr[2 * nt + 1][1] = r3;
                    }
#pragma unroll
                    for (int mi = 0; mi < 3; mi++)
#pragma unroll
                        for (int nj = 0; nj < 4; nj++)
                            MMA16816(acc[mi][nj], af[mi], bfr[nj]);
                }
            }
            asm volatile("cp.async.wait_group 0;" ::: "memory");

            // store accumulators into S_tile
            float* S = (float*)(smem + OFF_S0 + tile * SBYTES);
#pragma unroll
            for (int mi = 0; mi < 3; mi++) {
#pragma unroll
                for (int nj = 0; nj < 4; nj++) {
                    int row = wm * 48 + mi * 16 + (lane >> 2);
                    int col = wn * 32 + nj * 8 + (lane & 3) * 2;
                    *(float2*)&S[row * PS2 + col] =
                        make_float2(acc[mi][nj][0], acc[mi][nj][1]);
                    *(float2*)&S[(row + 8) * PS2 + col] =
                        make_float2(acc[mi][nj][2], acc[mi][nj][3]);
                }
            }
            BAR_SYNC(3, 192);   // all producer stores complete (and drained)
            if (tile == 0) { BAR_ARRIVE(1, 288); }
            else           { BAR_ARRIVE(2, 288); }
        }
    } else {
        // ================= CONSUMER (3 warps, 96 threads) =================
        const int t = tid - 192;
        const int lane = t & 31, gw = t >> 5;
        float* Gis = (float*)(smem + OFF_GI);
        float* Gcs = (float*)(smem + OFF_GC);
        {
            const float4* gi4 = (const float4*)(d_Gi + (size_t)(blockIdx.y * 4) * 1296);
            float4* dsti = (float4*)Gis;
            for (int idx = t; idx < 4 * 324; idx += 96) dsti[idx] = gi4[idx];
            const float4* gc4 = (const float4*)(d_Gc + (size_t)(blockIdx.x * 4) * 1024);
            float4* dstc = (float4*)Gcs;
            for (int idx = t; idx < 4 * 256; idx += 96) dstc[idx] = gc4[idx];
        }
        BAR_SYNC(4, 96);

        float* misc = (float*)(smem + OFF_MISC);
        float* irt = misc;           // [36]
        float* iri = misc + 36;      // [32]
        float* red = misc + 68;      // [3]

        for (int tile = 0; tile < 2; tile++) {
            if (tile == 0) { BAR_SYNC(1, 288); }
            else           { BAR_SYNC(2, 288); }
            float* S = (float*)(smem + OFF_S0 + tile * SBYTES);

#pragma unroll 1
            for (int pair = 0; pair < 8; pair++) {
                const int ii = pair >> 1, cc = pair & 1;
                float* Sp = S + (ii * 36) * PS2 + cc * 32;
                const float* Gip = Gis + ii * 1296;
                const float* Gcp = Gcs + (tile * 2 + cc) * 1024;

                // norms
                if (t < 36) {
                    float s0 = 0.f, s1 = 0.f;
#pragma unroll
                    for (int w = 0; w < 32; w += 2) {
                        float v0 = lrelu(Sp[t * PS2 + w]);     s0 += v0 * v0;
                        float v1 = lrelu(Sp[t * PS2 + w + 1]); s1 += v1 * v1;
                    }
                    irt[t] = __fdividef(1.f, sqrtf(s0 + s1) + EPSV);
                } else if (t < 68) {
                    int w = t - 36;
                    float s0 = 0.f, s1 = 0.f;
#pragma unroll
                    for (int r = 0; r < 36; r += 2) {
                        float v0 = lrelu(Sp[r * PS2 + w]);       s0 += v0 * v0;
                        float v1 = lrelu(Sp[(r + 1) * PS2 + w]); s1 += v1 * v1;
                    }
                    iri[w] = __fdividef(1.f, sqrtf(s0 + s1) + EPSV);
                }
                BAR_SYNC(4, 96);

                float val = 0.f;
                if (gw == 0) {
                    // t2i: query = word (lane)
                    const int w = lane;
                    float a[36];
                    float mx = -1e30f;
#pragma unroll
                    for (int r = 0; r < 36; r++) {
                        float v = lrelu(Sp[r * PS2 + w]) * irt[r];
                        a[r] = v; mx = fmaxf(mx, v);
                    }
                    float esum = 0.f;
#pragma unroll
                    for (int r = 0; r < 36; r++) { float e = __expf(LAMBDA * (a[r] - mx)); a[r] = e; esum += e; }
                    float th = esum * (1.f / 36.f), tsum = 0.f;
#pragma unroll
                    for (int r = 0; r < 36; r++) { float v = (a[r] > th) ? a[r] : 0.f; a[r] = v; tsum += v; }
                    float inv = __fdividef(1.f, tsum), num = 0.f;
#pragma unroll
                    for (int r = 0; r < 36; r++) { a[r] *= inv; num += a[r] * Sp[r * PS2 + w]; }
                    uint64_t a2[18];
#pragma unroll
                    for (int q = 0; q < 18; q++) a2[q] = f2pack(a[2 * q], a[2 * q + 1]);
                    float den0 = 0.f, den1 = 0.f;
#pragma unroll
                    for (int r = 0; r < 36; r += 2) {
                        const ulonglong2* Gr0 = (const ulonglong2*)(Gip + r * 36);
                        const ulonglong2* Gr1 = (const ulonglong2*)(Gip + (r + 1) * 36);
                        uint64_t xa = 0, xb = 0, za = 0, zb = 0;
#pragma unroll
                        for (int q = 0; q < 9; q++) {
                            ulonglong2 g0 = Gr0[q], g1 = Gr1[q];
                            ffma2(xa, g0.x, a2[2 * q]);
                            ffma2(xb, g0.y, a2[2 * q + 1]);
                            ffma2(za, g1.x, a2[2 * q]);
                            ffma2(zb, g1.y, a2[2 * q + 1]);
                        }
                        den0 += a[r] * (f2sum(xa) + f2sum(xb));
                        den1 += a[r + 1] * (f2sum(za) + f2sum(zb));
                    }
                    float den = den0 + den1;
                    val = num * __fdividef(1.f,
                          fmaxf(sqrtf(Gcp[w * 32 + w]), EPSV) * fmaxf(sqrtf(den), EPSV));
                } else {
                    // i2t: query = region
                    const bool valid = (gw == 1) || (lane < 4);
                    const int r = valid ? ((gw == 1) ? lane : 32 + lane) : 35;
                    float a[32];
                    float mx = -1e30f;
#pragma unroll
                    for (int w = 0; w < 32; w++) {
                        float v = lrelu(Sp[r * PS2 + w]) * iri[w];
                        a[w] = v; mx = fmaxf(mx, v);
                    }
                    float esum = 0.f;
#pragma unroll
                    for (int w = 0; w < 32; w++) { float e = __expf(LAMBDA * (a[w] - mx)); a[w] = e; esum += e; }
                    float th = esum * (1.f / 32.f), tsum = 0.f;
#pragma unroll
                    for (int w = 0; w < 32; w++) { float v = (a[w] > th) ? a[w] : 0.f; a[w] = v; tsum += v; }
                    float inv = __fdividef(1.f, tsum), num = 0.f;
#pragma unroll
                    for (int w = 0; w < 32; w++) { a[w] *= inv; num += a[w] * Sp[r * PS2 + w]; }
                    uint64_t a2[16];
#pragma unroll
                    for (int q = 0; q < 16; q++) a2[q] = f2pack(a[2 * q], a[2 * q + 1]);
                    float den0 = 0.f, den1 = 0.f;
#pragma unroll
                    for (int w = 0; w < 32; w += 2) {
                        const ulonglong2* Gr0 = (const ulonglong2*)(Gcp + w * 32);
                        const ulonglong2* Gr1 = (const ulonglong2*)(Gcp + (w + 1) * 32);
                        uint64_t xa = 0, xb = 0, za = 0, zb = 0;
#pragma unroll
                        for (int q = 0; q < 8; q++) {
                            ulonglong2 g0 = Gr0[q], g1 = Gr1[q];
                            ffma2(xa, g0.x, a2[2 * q]);
                            ffma2(xb, g0.y, a2[2 * q + 1]);
                            ffma2(za, g1.x, a2[2 * q]);
                            ffma2(zb, g1.y, a2[2 * q + 1]);
                        }
                        den0 += a[w] * (f2sum(xa) + f2sum(xb));
                        den1 += a[w + 1] * (f2sum(za) + f2sum(zb));
                    }
                    float den = den0 + den1;
                    float v = num * __fdividef(1.f,
                              fmaxf(sqrtf(Gip[r * 36 + r]), EPSV) * fmaxf(sqrtf(den), EPSV));
                    val = valid ? v : 0.f;
                }

#pragma unroll
                for (int off = 16; off > 0; off >>= 1)
                    val += __shfl_xor_sync(0xFFFFFFFFu, val, off);
                if (lane == 0) red[gw] = val;
                BAR_SYNC(4, 96);
                if (t == 0) {
                    int img = blockIdx.y * 4 + ii;
                    int cap = blockIdx.x * 4 + tile * 2 + cc;
                    out[img * N_CAP + cap] =
                        red[0] * (1.f / 32.f) + (red[1] + red[2]) * (1.f / 36.f);
                }
            }
        }
    }
}

// ---------------------------------------------------------------------------
extern "C" void kernel_launch(void* const* d_in, const int* in_sizes, int n_in,
                              void* d_out, int out_size) {
    const float* images   = (const float*)d_in[0];
    const float* captions = (const float*)d_in[1];
    float* out = (float*)d_out;

    prep_kernel<<<(M_TOT * DIM / 2) / 256, 256>>>(images, M_TOT * DIM / 2, 0);
    prep_kernel<<<(N_TOT * DIM / 2) / 256, 256>>>(captions, N_TOT * DIM / 2, 1);
    gram2_kernel<<<256, 256>>>(images, captions);

    cudaFuncSetAttribute(fused_kernel, cudaFuncAttributeMaxDynamicSharedMemorySize, FSMEM);
    dim3 fgrid(N_TOT / 128, M_TOT / 144);   // (32, 32)
    fused_kernel<<<fgrid, 288, FSMEM>>>(out);
}